// round 12
// baseline (speedup 1.0000x reference)
#include <cuda_runtime.h>
#include <cstddef>
#include <cstdint>

// LocalAttention: B=4, S=2048, D=256, W=33
// out = [values (B,S,D) | p_attn (B,S,W)] as float32

#define S_LEN   2048
#define D_DIM   256
#define B_SZ    4
#define W_SZ    33
#define HALF_W  16
#define TILE_Q  32
#define THREADS 256                // 8 warps
#define QW      4                  // queries per warp (halo efficiency preserved)
#define ROWS    (TILE_Q + 2*HALF_W)  // 64 K/V rows (single shared buffer)
#define D4      (D_DIM/4)          // 64 16B-chunks per row
#define NR      (QW + 2*HALF_W)    // 36 rows per warp
#define NW      (THREADS/32)       // 8 warps

// smem: shared KV buffer + score partials [NW][NR][4][2] + final p [NW][NR][4] + flags
#define SMEM_BYTES (ROWS*D_DIM*4 + NW*NR*8*4 + NW*NR*4*4 + ROWS*4)

typedef unsigned long long ull;

__device__ __forceinline__ ull fma2(ull a, ull b, ull c) {
    ull d;
    asm("fma.rn.f32x2 %0, %1, %2, %3;" : "=l"(d) : "l"(a), "l"(b), "l"(c));
    return d;
}
__device__ __forceinline__ float f32x2_sum(ull v) {
    float lo, hi;
    asm("mov.b64 {%0, %1}, %2;" : "=f"(lo), "=f"(hi) : "l"(v));
    return lo + hi;
}
__device__ __forceinline__ ull pack2(float x) {
    ull d;
    asm("mov.b64 %0, {%1, %1};" : "=l"(d) : "f"(x));
    return d;
}
__device__ __forceinline__ void cp16(void* smem_dst, const void* gsrc) {
    uint32_t s = (uint32_t)__cvta_generic_to_shared(smem_dst);
    asm volatile("cp.async.cg.shared.global [%0], [%1], 16;" :: "r"(s), "l"(gsrc));
}

__global__ void __launch_bounds__(THREADS, 2)
local_attn_kernel(const float* __restrict__ qg,
                  const float* __restrict__ kg,
                  const float* __restrict__ vg,
                  const int*   __restrict__ maskg,
                  float* __restrict__ out_vals,
                  float* __restrict__ out_p)
{
    extern __shared__ float smem[];
    float4* KVsm = reinterpret_cast<float4*>(smem);              // [ROWS][D4] (K, then V)
    float*  S2P  = reinterpret_cast<float*>(KVsm + ROWS * D4);   // [NW][NR][4][2]
    float*  PF   = S2P + NW * NR * 8;                            // [NW][NR][4]
    int*    Fsm  = reinterpret_cast<int*>(PF + NW * NR * 4);     // [ROWS]

    const int tile = blockIdx.x;           // 0..63
    const int b    = blockIdx.y;           // 0..3
    const int base = tile * TILE_Q;
    const int r0   = base - HALF_W;
    const int tid  = threadIdx.x;

    const float4* kg4 = reinterpret_cast<const float4*>(kg + (size_t)b * S_LEN * D_DIM);
    const float4* vg4 = reinterpret_cast<const float4*>(vg + (size_t)b * S_LEN * D_DIM);

    // ---- async-stage K into the shared buffer ----
    #pragma unroll
    for (int it = 0; it < ROWS * D4 / THREADS; ++it) {   // 16 iters
        int idx  = tid + it * THREADS;
        int row  = idx >> 6;
        int col  = idx & (D4 - 1);
        int grow = r0 + row;
        int gcl  = grow < 0 ? 0 : (grow >= S_LEN ? S_LEN - 1 : grow);
        cp16(KVsm + idx, kg4 + (size_t)gcl * D4 + col);
    }
    asm volatile("cp.async.commit_group;" ::: "memory");

    // ---- mask flags (during cp.async flight) ----
    if (tid < ROWS) {
        int grow = r0 + tid;
        int f = 0;
        if (grow >= 0 && grow < S_LEN) f = (maskg[b * S_LEN + grow] != 0);
        Fsm[tid] = f;
    }

    const int warp = tid >> 5;       // 0..7
    const int lane = tid & 31;
    const int lq0  = warp * QW;      // 0..28
    float* s2p = S2P + warp * NR * 8;    // this warp's partials [NR][4][2]
    float* pf  = PF  + warp * NR * 4;    // this warp's final p  [NR][4]

    // zero final-p block (out-of-window slots read by pass 2 must be 0)
    #pragma unroll
    for (int i = lane; i < NR * 4; i += 32) pf[i] = 0.f;

    // pass-1 lane decomposition: h = row of pair, p = 16-lane d-position
    const int h  = lane >> 4;
    const int p  = lane & 15;
    const int b3 = (p >> 3) & 1;
    const int b2 = (p >> 2) & 1;
    const int qcar = (b2 << 1) | b3;          // query this lane carries after reduce

    // ---- Q fragments (LDG overlaps the cp.async drain) ----
    ulonglong2 qf[QW][4];
    {
        const ulonglong2* qb = reinterpret_cast<const ulonglong2*>(
            qg + ((size_t)b * S_LEN + base + lq0) * D_DIM);
        #pragma unroll
        for (int q = 0; q < QW; ++q)
            #pragma unroll
            for (int c = 0; c < 4; ++c)
                qf[q][c] = qb[q * D4 + p + 16 * c];
    }

    asm volatile("cp.async.wait_group 0;" ::: "memory");
    __syncthreads();

    const ulonglong2* Ksm2 = reinterpret_cast<const ulonglong2*>(KVsm);

    // ---- pass 1: 2 rows/iter, K double-buffered in regs, 3-level reduce ----
    ulonglong2 k0, k1, k2, k3;
    {
        const ulonglong2* krow = Ksm2 + (size_t)(lq0 + h) * D4 + p;
        k0 = krow[0]; k1 = krow[16]; k2 = krow[32]; k3 = krow[48];
    }
    #pragma unroll 2
    for (int ri = 0; ri < NR / 2; ++ri) {   // 18 iters
        ulonglong2 n0, n1, n2, n3;
        if (ri + 1 < NR / 2) {
            const ulonglong2* kn = Ksm2 + (size_t)(lq0 + 2 * (ri + 1) + h) * D4 + p;
            n0 = kn[0]; n1 = kn[16]; n2 = kn[32]; n3 = kn[48];
        }

        float s[QW];
        #pragma unroll
        for (int q = 0; q < QW; ++q) {
            ull a0 = fma2(k0.x, qf[q][0].x, 0ull);
            ull a1 = fma2(k0.y, qf[q][0].y, 0ull);
            a0 = fma2(k1.x, qf[q][1].x, a0);
            a1 = fma2(k1.y, qf[q][1].y, a1);
            a0 = fma2(k2.x, qf[q][2].x, a0);
            a1 = fma2(k2.y, qf[q][2].y, a1);
            a0 = fma2(k3.x, qf[q][3].x, a0);
            a1 = fma2(k3.y, qf[q][3].y, a1);
            s[q] = f32x2_sum(a0) + f32x2_sum(a1);
        }

        // level xor8 (bit3): pair (s0,s1) and (s2,s3)
        float xA_keep = b3 ? s[1] : s[0];
        float xA_send = b3 ? s[0] : s[1];
        float xB_keep = b3 ? s[3] : s[2];
        float xB_send = b3 ? s[2] : s[3];
        float xA = xA_keep + __shfl_xor_sync(0xffffffffu, xA_send, 8);
        float xB = xB_keep + __shfl_xor_sync(0xffffffffu, xB_send, 8);
        // level xor4 (bit2): pair (xA, xB) -> query qcar over 4 lanes
        float z_keep = b2 ? xB : xA;
        float z_send = b2 ? xA : xB;
        float z = z_keep + __shfl_xor_sync(0xffffffffu, z_send, 4);
        // level xor2: -> 2 remaining partials (p&1)
        z += __shfl_xor_sync(0xffffffffu, z, 2);

        int rl = 2 * ri + h;
        int wpos = rl - qcar;
        if ((p & 2) == 0 && wpos >= 0 && wpos < W_SZ) {
            s2p[rl * 8 + qcar * 2 + (p & 1)] = z;   // raw partial (scale+mask later)
        }

        k0 = n0; k1 = n1; k2 = n2; k3 = n3;
    }
    __syncthreads();   // ALL warps done reading K before V overwrites the buffer

    // ---- async-stage V into the same buffer; softmax overlaps the flight ----
    #pragma unroll
    for (int it = 0; it < ROWS * D4 / THREADS; ++it) {   // 16 iters
        int idx  = tid + it * THREADS;
        int row  = idx >> 6;
        int col  = idx & (D4 - 1);
        int grow = r0 + row;
        int gcl  = grow < 0 ? 0 : (grow >= S_LEN ? S_LEN - 1 : grow);
        cp16(KVsm + idx, vg4 + (size_t)gcl * D4 + col);
    }
    asm volatile("cp.async.commit_group;" ::: "memory");

    // ---- warp-local softmax: 8 lanes per query; sum partials + scale + mask ----
    const int g8 = lane >> 3;
    const int j  = lane & 7;
    const int gq = base + lq0 + g8;
    {
        const float* pb = s2p + g8 * 2;
        int m0 = g8 + j;
        float s0 = Fsm[lq0 + m0]      ? (pb[m0 * 8] + pb[m0 * 8 + 1]) * 0.0625f : -1e10f;
        float s1 = Fsm[lq0 + m0 + 8]  ? (pb[(m0 + 8) * 8] + pb[(m0 + 8) * 8 + 1]) * 0.0625f : -1e10f;
        float s2 = Fsm[lq0 + m0 + 16] ? (pb[(m0 + 16) * 8] + pb[(m0 + 16) * 8 + 1]) * 0.0625f : -1e10f;
        float s3 = Fsm[lq0 + m0 + 24] ? (pb[(m0 + 24) * 8] + pb[(m0 + 24) * 8 + 1]) * 0.0625f : -1e10f;
        float s4 = -3e38f;
        if (j == 0) {
            int m4 = g8 + 32;
            s4 = Fsm[lq0 + m4] ? (pb[m4 * 8] + pb[m4 * 8 + 1]) * 0.0625f : -1e10f;
        }

        float mx = fmaxf(fmaxf(fmaxf(s0, s1), fmaxf(s2, s3)), s4);
        mx = fmaxf(mx, __shfl_xor_sync(0xffffffffu, mx, 4));
        mx = fmaxf(mx, __shfl_xor_sync(0xffffffffu, mx, 2));
        mx = fmaxf(mx, __shfl_xor_sync(0xffffffffu, mx, 1));

        float e0 = __expf(s0 - mx);
        float e1 = __expf(s1 - mx);
        float e2 = __expf(s2 - mx);
        float e3 = __expf(s3 - mx);
        float e4 = (j == 0) ? __expf(s4 - mx) : 0.f;

        float sum = ((e0 + e1) + (e2 + e3)) + e4;
        sum += __shfl_xor_sync(0xffffffffu, sum, 4);
        sum += __shfl_xor_sync(0xffffffffu, sum, 2);
        sum += __shfl_xor_sync(0xffffffffu, sum, 1);
        float inv = 1.f / sum;

        float p0 = e0 * inv, p1 = e1 * inv, p2 = e2 * inv, p3 = e3 * inv;
        pf[m0 * 4 + g8]        = p0;
        pf[(m0 + 8) * 4 + g8]  = p1;
        pf[(m0 + 16) * 4 + g8] = p2;
        pf[(m0 + 24) * 4 + g8] = p3;

        float* po = out_p + (size_t)(b * S_LEN + gq) * W_SZ;
        po[j]      = p0;
        po[j + 8]  = p1;
        po[j + 16] = p2;
        po[j + 24] = p3;
        if (j == 0) {
            float p4 = e4 * inv;
            pf[(g8 + 32) * 4 + g8] = p4;
            po[32] = p4;
        }
    }

    // V resident + visible block-wide before pass 2
    asm volatile("cp.async.wait_group 0;" ::: "memory");
    __syncthreads();

    // ---- pass 2: V rows + p float4 both prefetched ----
    ulonglong2 acc[QW][2];
    #pragma unroll
    for (int q = 0; q < QW; ++q) {
        acc[q][0].x = 0ull; acc[q][0].y = 0ull;
        acc[q][1].x = 0ull; acc[q][1].y = 0ull;
    }

    const ulonglong2* Vsm2 = reinterpret_cast<const ulonglong2*>(KVsm);
    const float4* pf4 = reinterpret_cast<const float4*>(pf);

    ulonglong2 v0 = Vsm2[(size_t)lq0 * D4 + 2 * lane];
    ulonglong2 v1 = Vsm2[(size_t)lq0 * D4 + 2 * lane + 1];
    float4 pv = pf4[0];

    #pragma unroll 4
    for (int r = 0; r < NR; ++r) {   // 36
        ulonglong2 v0n, v1n;
        float4 pvn;
        if (r + 1 < NR) {
            const ulonglong2* vn = Vsm2 + (size_t)(lq0 + r + 1) * D4 + 2 * lane;
            v0n = vn[0];
            v1n = vn[1];
            pvn = pf4[r + 1];
        }
        ull pp0 = pack2(pv.x);
        ull pp1 = pack2(pv.y);
        ull pp2 = pack2(pv.z);
        ull pp3 = pack2(pv.w);
        acc[0][0].x = fma2(pp0, v0.x, acc[0][0].x);
        acc[0][0].y = fma2(pp0, v0.y, acc[0][0].y);
        acc[0][1].x = fma2(pp0, v1.x, acc[0][1].x);
        acc[0][1].y = fma2(pp0, v1.y, acc[0][1].y);
        acc[1][0].x = fma2(pp1, v0.x, acc[1][0].x);
        acc[1][0].y = fma2(pp1, v0.y, acc[1][0].y);
        acc[1][1].x = fma2(pp1, v1.x, acc[1][1].x);
        acc[1][1].y = fma2(pp1, v1.y, acc[1][1].y);
        acc[2][0].x = fma2(pp2, v0.x, acc[2][0].x);
        acc[2][0].y = fma2(pp2, v0.y, acc[2][0].y);
        acc[2][1].x = fma2(pp2, v1.x, acc[2][1].x);
        acc[2][1].y = fma2(pp2, v1.y, acc[2][1].y);
        acc[3][0].x = fma2(pp3, v0.x, acc[3][0].x);
        acc[3][0].y = fma2(pp3, v0.y, acc[3][0].y);
        acc[3][1].x = fma2(pp3, v1.x, acc[3][1].x);
        acc[3][1].y = fma2(pp3, v1.y, acc[3][1].y);
        v0 = v0n;
        v1 = v1n;
        pv = pvn;
    }

    ulonglong2* obase = reinterpret_cast<ulonglong2*>(
        out_vals + ((size_t)b * S_LEN + base + lq0) * D_DIM);
    #pragma unroll
    for (int q = 0; q < QW; ++q) {
        obase[q * D4 + 2 * lane]     = acc[q][0];
        obase[q * D4 + 2 * lane + 1] = acc[q][1];
    }
}

extern "C" void kernel_launch(void* const* d_in, const int* in_sizes, int n_in,
                              void* d_out, int out_size)
{
    const float* q    = (const float*)d_in[0];
    const float* k    = (const float*)d_in[1];
    const float* v    = (const float*)d_in[2];
    const int*   mask = (const int*)d_in[3];

    float* out_vals = (float*)d_out;
    float* out_p    = out_vals + (size_t)B_SZ * S_LEN * D_DIM;

    static bool attr_set = false;
    if (!attr_set) {
        cudaFuncSetAttribute(local_attn_kernel,
                             cudaFuncAttributeMaxDynamicSharedMemorySize,
                             SMEM_BYTES);
        attr_set = true;
    }

    dim3 grid(S_LEN / TILE_Q, B_SZ);   // (64, 4) = 256 CTAs, 2 per SM on most SMs
    local_attn_kernel<<<grid, THREADS, SMEM_BYTES>>>(q, k, v, mask, out_vals, out_p);
}

// round 13
// speedup vs baseline: 1.4585x; 1.4585x over previous
#include <cuda_runtime.h>
#include <cstddef>
#include <cstdint>

// LocalAttention: B=4, S=2048, D=256, W=33
// out = [values (B,S,D) | p_attn (B,S,W)] as float32

#define S_LEN   2048
#define D_DIM   256
#define B_SZ    4
#define W_SZ    33
#define HALF_W  16
#define TILE_Q  64
#define THREADS 512                // 16 warps
#define QW      4                  // queries per warp
#define ROWS    (TILE_Q + 2*HALF_W)  // 96 K/V rows in smem
#define D4      (D_DIM/4)          // 64 16B-chunks per row
#define NR      (QW + 2*HALF_W)    // 36 rows per warp
#define NW      (THREADS/32)       // 16 warps

// smem: K + V + score-partials/p (aliased) [NW][NR][4][2]f + flags
#define SMEM_BYTES (ROWS*D_DIM*4*2 + NW*NR*8*4 + ROWS*4)

typedef unsigned long long ull;

__device__ __forceinline__ ull fma2(ull a, ull b, ull c) {
    ull d;
    asm("fma.rn.f32x2 %0, %1, %2, %3;" : "=l"(d) : "l"(a), "l"(b), "l"(c));
    return d;
}
__device__ __forceinline__ float f32x2_sum(ull v) {
    float lo, hi;
    asm("mov.b64 {%0, %1}, %2;" : "=f"(lo), "=f"(hi) : "l"(v));
    return lo + hi;
}
__device__ __forceinline__ ull pack2(float x) {
    ull d;
    asm("mov.b64 %0, {%1, %1};" : "=l"(d) : "f"(x));
    return d;
}
__device__ __forceinline__ void cp16(void* smem_dst, const void* gsrc) {
    uint32_t s = (uint32_t)__cvta_generic_to_shared(smem_dst);
    asm volatile("cp.async.cg.shared.global [%0], [%1], 16;" :: "r"(s), "l"(gsrc));
}

__global__ void __launch_bounds__(THREADS, 1)
local_attn_kernel(const float* __restrict__ qg,
                  const float* __restrict__ kg,
                  const float* __restrict__ vg,
                  const int*   __restrict__ maskg,
                  float* __restrict__ out_vals,
                  float* __restrict__ out_p)
{
    extern __shared__ float smem[];
    float4* Ksm = reinterpret_cast<float4*>(smem);
    float4* Vsm = Ksm + ROWS * D4;
    float*  S2P = reinterpret_cast<float*>(Vsm + ROWS * D4);   // [NW][NR][4][2] (later p-pairs)
    int*    Fsm = reinterpret_cast<int*>(S2P + NW * NR * 8);   // [ROWS]

    const int tile = blockIdx.x;
    const int b    = blockIdx.y;
    const int base = tile * TILE_Q;
    const int r0   = base - HALF_W;
    const int tid  = threadIdx.x;

    const float4* kg4 = reinterpret_cast<const float4*>(kg + (size_t)b * S_LEN * D_DIM);
    const float4* vg4 = reinterpret_cast<const float4*>(vg + (size_t)b * S_LEN * D_DIM);

    // ---- async-stage K (group 0) ----
    #pragma unroll
    for (int it = 0; it < ROWS * D4 / THREADS; ++it) {   // 12 iters
        int idx  = tid + it * THREADS;
        int row  = idx >> 6;
        int col  = idx & (D4 - 1);
        int grow = r0 + row;
        int gcl  = grow < 0 ? 0 : (grow >= S_LEN ? S_LEN - 1 : grow);
        cp16(Ksm + idx, kg4 + (size_t)gcl * D4 + col);
    }
    asm volatile("cp.async.commit_group;" ::: "memory");

    // ---- async-stage V (group 1; waited before pass 2) ----
    #pragma unroll
    for (int it = 0; it < ROWS * D4 / THREADS; ++it) {
        int idx  = tid + it * THREADS;
        int row  = idx >> 6;
        int col  = idx & (D4 - 1);
        int grow = r0 + row;
        int gcl  = grow < 0 ? 0 : (grow >= S_LEN ? S_LEN - 1 : grow);
        cp16(Vsm + idx, vg4 + (size_t)gcl * D4 + col);
    }
    asm volatile("cp.async.commit_group;" ::: "memory");

    // ---- mask flags (during cp.async flight) ----
    if (tid < ROWS) {
        int grow = r0 + tid;
        int f = 0;
        if (grow >= 0 && grow < S_LEN) f = (maskg[b * S_LEN + grow] != 0);
        Fsm[tid] = f;
    }

    const int warp = tid >> 5;
    const int lane = tid & 31;
    const int lq0  = warp * QW;
    float* s2p = S2P + warp * NR * 8;    // this warp's partial/p block

    // zero the block: out-of-window slots must read as p=0 in pass 2
    #pragma unroll
    for (int i = lane; i < NR * 8; i += 32) s2p[i] = 0.f;

    // pass-1 lane decomposition: h = row of pair, p = 16-lane d-position
    const int h  = lane >> 4;
    const int p  = lane & 15;
    const int b3 = (p >> 3) & 1;
    const int b2 = (p >> 2) & 1;
    const int qcar = (b2 << 1) | b3;          // query this lane carries after reduce

    // ---- Q fragments (LDG overlaps the cp.async drain) ----
    ulonglong2 qf[QW][4];
    {
        const ulonglong2* qb = reinterpret_cast<const ulonglong2*>(
            qg + ((size_t)b * S_LEN + base + lq0) * D_DIM);
        #pragma unroll
        for (int q = 0; q < QW; ++q)
            #pragma unroll
            for (int c = 0; c < 4; ++c)
                qf[q][c] = qb[q * D4 + p + 16 * c];
    }

    // wait for K (V still in flight), then block-sync (also orders zeroing)
    asm volatile("cp.async.wait_group 1;" ::: "memory");
    __syncthreads();

    const ulonglong2* Ksm2 = reinterpret_cast<const ulonglong2*>(Ksm);

    // ---- pass 1: 2 rows/iter, 3-level pair-compressed reduce to 2 partials ----
    #pragma unroll 6
    for (int ri = 0; ri < NR / 2; ++ri) {   // 18 iters
        int m = lq0 + 2 * ri + h;
        const ulonglong2* krow = Ksm2 + (size_t)m * D4 + p;
        ulonglong2 k0 = krow[0];
        ulonglong2 k1 = krow[16];
        ulonglong2 k2 = krow[32];
        ulonglong2 k3 = krow[48];

        float s[QW];
        #pragma unroll
        for (int q = 0; q < QW; ++q) {
            ull a0 = fma2(k0.x, qf[q][0].x, 0ull);
            ull a1 = fma2(k0.y, qf[q][0].y, 0ull);
            a0 = fma2(k1.x, qf[q][1].x, a0);
            a1 = fma2(k1.y, qf[q][1].y, a1);
            a0 = fma2(k2.x, qf[q][2].x, a0);
            a1 = fma2(k2.y, qf[q][2].y, a1);
            a0 = fma2(k3.x, qf[q][3].x, a0);
            a1 = fma2(k3.y, qf[q][3].y, a1);
            s[q] = f32x2_sum(a0) + f32x2_sum(a1);
        }

        // level xor8 (bit3): pair (s0,s1) and (s2,s3)
        float xA_keep = b3 ? s[1] : s[0];
        float xA_send = b3 ? s[0] : s[1];
        float xB_keep = b3 ? s[3] : s[2];
        float xB_send = b3 ? s[2] : s[3];
        float xA = xA_keep + __shfl_xor_sync(0xffffffffu, xA_send, 8);
        float xB = xB_keep + __shfl_xor_sync(0xffffffffu, xB_send, 8);
        // level xor4 (bit2): pair (xA, xB) -> query qcar over 4 lanes
        float z_keep = b2 ? xB : xA;
        float z_send = b2 ? xA : xB;
        float z = z_keep + __shfl_xor_sync(0xffffffffu, z_send, 4);
        // level xor2: -> 2 remaining partials (p&1)
        z += __shfl_xor_sync(0xffffffffu, z, 2);

        int rl = 2 * ri + h;
        int wpos = rl - qcar;
        if ((p & 2) == 0 && wpos >= 0 && wpos < W_SZ) {
            s2p[rl * 8 + qcar * 2 + (p & 1)] = z;   // raw partial (scale+mask later)
        }
    }
    __syncwarp();

    // ---- warp-local softmax: 8 lanes per query; float2 partial loads;
    //      writes packed (p,p) ulls IN PLACE (same lane's own slots) ----
    const int g8 = lane >> 3;
    const int j  = lane & 7;
    const int gq = base + lq0 + g8;
    {
        const float2* pb2 = reinterpret_cast<const float2*>(s2p);  // [NR][4] pairs
        ull* pf2 = reinterpret_cast<ull*>(s2p);                    // [NR][4] packed p
        int m0 = g8 + j;
        float2 t0 = pb2[m0 * 4 + g8];
        float2 t1 = pb2[(m0 + 8) * 4 + g8];
        float2 t2 = pb2[(m0 + 16) * 4 + g8];
        float2 t3 = pb2[(m0 + 24) * 4 + g8];
        float s0 = Fsm[lq0 + m0]      ? (t0.x + t0.y) * 0.0625f : -1e10f;
        float s1 = Fsm[lq0 + m0 + 8]  ? (t1.x + t1.y) * 0.0625f : -1e10f;
        float s2 = Fsm[lq0 + m0 + 16] ? (t2.x + t2.y) * 0.0625f : -1e10f;
        float s3 = Fsm[lq0 + m0 + 24] ? (t3.x + t3.y) * 0.0625f : -1e10f;
        float s4 = -3e38f;
        if (j == 0) {
            float2 t4 = pb2[(g8 + 32) * 4 + g8];
            s4 = Fsm[lq0 + g8 + 32] ? (t4.x + t4.y) * 0.0625f : -1e10f;
        }

        float mx = fmaxf(fmaxf(fmaxf(s0, s1), fmaxf(s2, s3)), s4);
        mx = fmaxf(mx, __shfl_xor_sync(0xffffffffu, mx, 4));
        mx = fmaxf(mx, __shfl_xor_sync(0xffffffffu, mx, 2));
        mx = fmaxf(mx, __shfl_xor_sync(0xffffffffu, mx, 1));

        float e0 = __expf(s0 - mx);
        float e1 = __expf(s1 - mx);
        float e2 = __expf(s2 - mx);
        float e3 = __expf(s3 - mx);
        float e4 = (j == 0) ? __expf(s4 - mx) : 0.f;

        float sum = ((e0 + e1) + (e2 + e3)) + e4;
        sum += __shfl_xor_sync(0xffffffffu, sum, 4);
        sum += __shfl_xor_sync(0xffffffffu, sum, 2);
        sum += __shfl_xor_sync(0xffffffffu, sum, 1);
        float inv = 1.f / sum;

        float p0 = e0 * inv, p1 = e1 * inv, p2 = e2 * inv, p3 = e3 * inv;
        pf2[m0 * 4 + g8]        = pack2(p0);
        pf2[(m0 + 8) * 4 + g8]  = pack2(p1);
        pf2[(m0 + 16) * 4 + g8] = pack2(p2);
        pf2[(m0 + 24) * 4 + g8] = pack2(p3);

        float* po = out_p + (size_t)(b * S_LEN + gq) * W_SZ;
        po[j]      = p0;
        po[j + 8]  = p1;
        po[j + 16] = p2;
        po[j + 24] = p3;
        if (j == 0) {
            float p4 = e4 * inv;
            pf2[(g8 + 32) * 4 + g8] = pack2(p4);
            po[32] = p4;
        }
    }

    // V resident + visible block-wide before pass 2 (also publishes pf2)
    asm volatile("cp.async.wait_group 0;" ::: "memory");
    __syncthreads();

    // ---- pass 2: 2 broadcast LDS.128 give packed p for all 4 queries ----
    ulonglong2 acc[QW][2];
    #pragma unroll
    for (int q = 0; q < QW; ++q) {
        acc[q][0].x = 0ull; acc[q][0].y = 0ull;
        acc[q][1].x = 0ull; acc[q][1].y = 0ull;
    }

    const ulonglong2* Vsm2 = reinterpret_cast<const ulonglong2*>(Vsm);
    const ulonglong2* pf2u = reinterpret_cast<const ulonglong2*>(s2p);  // [NR][2]

    #pragma unroll 6
    for (int r = 0; r < NR; ++r) {   // 36
        const ulonglong2* vrow = Vsm2 + (size_t)(lq0 + r) * D4 + 2 * lane;
        ulonglong2 v0 = vrow[0];
        ulonglong2 v1 = vrow[1];
        ulonglong2 pa = pf2u[r * 2];       // (p0,p0),(p1,p1)
        ulonglong2 pb = pf2u[r * 2 + 1];   // (p2,p2),(p3,p3)
        acc[0][0].x = fma2(pa.x, v0.x, acc[0][0].x);
        acc[0][0].y = fma2(pa.x, v0.y, acc[0][0].y);
        acc[0][1].x = fma2(pa.x, v1.x, acc[0][1].x);
        acc[0][1].y = fma2(pa.x, v1.y, acc[0][1].y);
        acc[1][0].x = fma2(pa.y, v0.x, acc[1][0].x);
        acc[1][0].y = fma2(pa.y, v0.y, acc[1][0].y);
        acc[1][1].x = fma2(pa.y, v1.x, acc[1][1].x);
        acc[1][1].y = fma2(pa.y, v1.y, acc[1][1].y);
        acc[2][0].x = fma2(pb.x, v0.x, acc[2][0].x);
        acc[2][0].y = fma2(pb.x, v0.y, acc[2][0].y);
        acc[2][1].x = fma2(pb.x, v1.x, acc[2][1].x);
        acc[2][1].y = fma2(pb.x, v1.y, acc[2][1].y);
        acc[3][0].x = fma2(pb.y, v0.x, acc[3][0].x);
        acc[3][0].y = fma2(pb.y, v0.y, acc[3][0].y);
        acc[3][1].x = fma2(pb.y, v1.x, acc[3][1].x);
        acc[3][1].y = fma2(pb.y, v1.y, acc[3][1].y);
    }

    ulonglong2* obase = reinterpret_cast<ulonglong2*>(
        out_vals + ((size_t)b * S_LEN + base + lq0) * D_DIM);
    #pragma unroll
    for (int q = 0; q < QW; ++q) {
        obase[q * D4 + 2 * lane]     = acc[q][0];
        obase[q * D4 + 2 * lane + 1] = acc[q][1];
    }
}

extern "C" void kernel_launch(void* const* d_in, const int* in_sizes, int n_in,
                              void* d_out, int out_size)
{
    const float* q    = (const float*)d_in[0];
    const float* k    = (const float*)d_in[1];
    const float* v    = (const float*)d_in[2];
    const int*   mask = (const int*)d_in[3];

    float* out_vals = (float*)d_out;
    float* out_p    = out_vals + (size_t)B_SZ * S_LEN * D_DIM;

    static bool attr_set = false;
    if (!attr_set) {
        cudaFuncSetAttribute(local_attn_kernel,
                             cudaFuncAttributeMaxDynamicSharedMemorySize,
                             SMEM_BYTES);
        attr_set = true;
    }

    dim3 grid(S_LEN / TILE_Q, B_SZ);   // (32, 4) = 128 CTAs, one wave
    local_attn_kernel<<<grid, THREADS, SMEM_BYTES>>>(q, k, v, mask, out_vals, out_p);
}

// round 14
// speedup vs baseline: 1.4741x; 1.0107x over previous
#include <cuda_runtime.h>
#include <cstddef>
#include <cstdint>

// LocalAttention: B=4, S=2048, D=256, W=33
// out = [values (B,S,D) | p_attn (B,S,W)] as float32

#define S_LEN   2048
#define D_DIM   256
#define B_SZ    4
#define W_SZ    33
#define HALF_W  16
#define TILE_Q  64
#define THREADS 512                // 16 warps
#define QW      4                  // queries per warp
#define ROWS    (TILE_Q + 2*HALF_W)  // 96 K/V rows in smem
#define D4      (D_DIM/4)          // 64 16B-chunks per row
#define NR      (QW + 2*HALF_W)    // 36 rows per warp
#define NW      (THREADS/32)       // 16 warps

// smem: K + V + score-partials/p-pairs (aliased) [NW][NR][4][2]f + flags
#define SMEM_BYTES (ROWS*D_DIM*4*2 + NW*NR*8*4 + ROWS*4)

typedef unsigned long long ull;

__device__ __forceinline__ ull fma2(ull a, ull b, ull c) {
    ull d;
    asm("fma.rn.f32x2 %0, %1, %2, %3;" : "=l"(d) : "l"(a), "l"(b), "l"(c));
    return d;
}
__device__ __forceinline__ ull add2(ull a, ull b) {
    ull d;
    asm("add.rn.f32x2 %0, %1, %2;" : "=l"(d) : "l"(a), "l"(b));
    return d;
}
__device__ __forceinline__ float f32x2_sum(ull v) {
    float lo, hi;
    asm("mov.b64 {%0, %1}, %2;" : "=f"(lo), "=f"(hi) : "l"(v));
    return lo + hi;
}
__device__ __forceinline__ ull pack2(float x) {
    ull d;
    asm("mov.b64 %0, {%1, %1};" : "=l"(d) : "f"(x));
    return d;
}
__device__ __forceinline__ void cp16(void* smem_dst, const void* gsrc) {
    uint32_t s = (uint32_t)__cvta_generic_to_shared(smem_dst);
    asm volatile("cp.async.cg.shared.global [%0], [%1], 16;" :: "r"(s), "l"(gsrc));
}

__global__ void __launch_bounds__(THREADS, 1)
local_attn_kernel(const float* __restrict__ qg,
                  const float* __restrict__ kg,
                  const float* __restrict__ vg,
                  const int*   __restrict__ maskg,
                  float* __restrict__ out_vals,
                  float* __restrict__ out_p)
{
    extern __shared__ float smem[];
    float4* Ksm = reinterpret_cast<float4*>(smem);
    float4* Vsm = Ksm + ROWS * D4;
    float*  S2P = reinterpret_cast<float*>(Vsm + ROWS * D4);   // [NW][NR][4][2] / p-pairs
    int*    Fsm = reinterpret_cast<int*>(S2P + NW * NR * 8);   // [ROWS]

    const int tile = blockIdx.x;
    const int b    = blockIdx.y;
    const int base = tile * TILE_Q;
    const int r0   = base - HALF_W;
    const int tid  = threadIdx.x;

    const float4* kg4 = reinterpret_cast<const float4*>(kg + (size_t)b * S_LEN * D_DIM);
    const float4* vg4 = reinterpret_cast<const float4*>(vg + (size_t)b * S_LEN * D_DIM);

    // ---- async-stage K (group 0) ----
    #pragma unroll
    for (int it = 0; it < ROWS * D4 / THREADS; ++it) {   // 12 iters
        int idx  = tid + it * THREADS;
        int row  = idx >> 6;
        int col  = idx & (D4 - 1);
        int grow = r0 + row;
        int gcl  = grow < 0 ? 0 : (grow >= S_LEN ? S_LEN - 1 : grow);
        cp16(Ksm + idx, kg4 + (size_t)gcl * D4 + col);
    }
    asm volatile("cp.async.commit_group;" ::: "memory");

    // ---- async-stage V (group 1; waited before pass 2) ----
    #pragma unroll
    for (int it = 0; it < ROWS * D4 / THREADS; ++it) {
        int idx  = tid + it * THREADS;
        int row  = idx >> 6;
        int col  = idx & (D4 - 1);
        int grow = r0 + row;
        int gcl  = grow < 0 ? 0 : (grow >= S_LEN ? S_LEN - 1 : grow);
        cp16(Vsm + idx, vg4 + (size_t)gcl * D4 + col);
    }
    asm volatile("cp.async.commit_group;" ::: "memory");

    // ---- mask flags (during cp.async flight) ----
    if (tid < ROWS) {
        int grow = r0 + tid;
        int f = 0;
        if (grow >= 0 && grow < S_LEN) f = (maskg[b * S_LEN + grow] != 0);
        Fsm[tid] = f;
    }

    const int warp = tid >> 5;
    const int lane = tid & 31;
    const int lq0  = warp * QW;
    float* s2p = S2P + warp * NR * 8;    // this warp's partial/p block

    // zero: out-of-window slots must read as p=0 in pass 2
    #pragma unroll
    for (int i = lane; i < NR * 8; i += 32) s2p[i] = 0.f;

    // pass-1 lane decomposition: h = row of pair, p = 16-lane d-position
    const int h  = lane >> 4;
    const int p  = lane & 15;
    const int b3 = (p >> 3) & 1;
    const int b2 = (p >> 2) & 1;
    const int qcar = (b2 << 1) | b3;          // query this lane carries after reduce

    // ---- Q fragments (LDG overlaps the cp.async drain) ----
    ulonglong2 qf[QW][4];
    {
        const ulonglong2* qb = reinterpret_cast<const ulonglong2*>(
            qg + ((size_t)b * S_LEN + base + lq0) * D_DIM);
        #pragma unroll
        for (int q = 0; q < QW; ++q)
            #pragma unroll
            for (int c = 0; c < 4; ++c)
                qf[q][c] = qb[q * D4 + p + 16 * c];
    }

    // wait for K (V still in flight), then block-sync (also orders zeroing)
    asm volatile("cp.async.wait_group 1;" ::: "memory");
    __syncthreads();

    const ulonglong2* Ksm2 = reinterpret_cast<const ulonglong2*>(Ksm);

    // ---- pass 1: 2 rows/iter, K double-buffered, 4 depth-2 FMA chains,
    //      3-serial-SHFL pair-compressed reduce to 2 partials ----
    ulonglong2 k0, k1, k2, k3;
    {
        const ulonglong2* krow = Ksm2 + (size_t)(lq0 + h) * D4 + p;
        k0 = krow[0]; k1 = krow[16]; k2 = krow[32]; k3 = krow[48];
    }
    #pragma unroll 4
    for (int ri = 0; ri < NR / 2; ++ri) {   // 18 iters
        ulonglong2 n0, n1, n2, n3;
        if (ri + 1 < NR / 2) {
            const ulonglong2* kn = Ksm2 + (size_t)(lq0 + 2 * (ri + 1) + h) * D4 + p;
            n0 = kn[0]; n1 = kn[16]; n2 = kn[32]; n3 = kn[48];
        }

        float s[QW];
        #pragma unroll
        for (int q = 0; q < QW; ++q) {
            ull a0 = fma2(k0.x, qf[q][0].x, 0ull);
            ull a1 = fma2(k0.y, qf[q][0].y, 0ull);
            ull a2 = fma2(k1.x, qf[q][1].x, 0ull);
            ull a3 = fma2(k1.y, qf[q][1].y, 0ull);
            a0 = fma2(k2.x, qf[q][2].x, a0);
            a1 = fma2(k2.y, qf[q][2].y, a1);
            a2 = fma2(k3.x, qf[q][3].x, a2);
            a3 = fma2(k3.y, qf[q][3].y, a3);
            s[q] = f32x2_sum(add2(a0, a2)) + f32x2_sum(add2(a1, a3));
        }

        // level xor8 (bit3): pair (s0,s1) and (s2,s3)
        float xA_keep = b3 ? s[1] : s[0];
        float xA_send = b3 ? s[0] : s[1];
        float xB_keep = b3 ? s[3] : s[2];
        float xB_send = b3 ? s[2] : s[3];
        float xA = xA_keep + __shfl_xor_sync(0xffffffffu, xA_send, 8);
        float xB = xB_keep + __shfl_xor_sync(0xffffffffu, xB_send, 8);
        // level xor4 (bit2): pair (xA, xB) -> query qcar over 4 lanes
        float z_keep = b2 ? xB : xA;
        float z_send = b2 ? xA : xB;
        float z = z_keep + __shfl_xor_sync(0xffffffffu, z_send, 4);
        // level xor2: -> 2 remaining partials (p&1)
        z += __shfl_xor_sync(0xffffffffu, z, 2);

        int rl = 2 * ri + h;
        int wpos = rl - qcar;
        if ((p & 2) == 0 && wpos >= 0 && wpos < W_SZ) {
            s2p[rl * 8 + qcar * 2 + (p & 1)] = z;   // raw partial (scale+mask later)
        }

        k0 = n0; k1 = n1; k2 = n2; k3 = n3;
    }
    __syncwarp();

    // ---- warp-local softmax: 8 lanes per query; float2 partial loads;
    //      writes packed (p,p) ulls IN PLACE ----
    const int g8 = lane >> 3;
    const int j  = lane & 7;
    const int gq = base + lq0 + g8;
    {
        const float2* pb2 = reinterpret_cast<const float2*>(s2p);  // [NR][4] pairs
        ull* pf2 = reinterpret_cast<ull*>(s2p);                    // [NR][4] packed p
        int m0 = g8 + j;
        float2 t0 = pb2[m0 * 4 + g8];
        float2 t1 = pb2[(m0 + 8) * 4 + g8];
        float2 t2 = pb2[(m0 + 16) * 4 + g8];
        float2 t3 = pb2[(m0 + 24) * 4 + g8];
        float s0 = Fsm[lq0 + m0]      ? (t0.x + t0.y) * 0.0625f : -1e10f;
        float s1 = Fsm[lq0 + m0 + 8]  ? (t1.x + t1.y) * 0.0625f : -1e10f;
        float s2 = Fsm[lq0 + m0 + 16] ? (t2.x + t2.y) * 0.0625f : -1e10f;
        float s3 = Fsm[lq0 + m0 + 24] ? (t3.x + t3.y) * 0.0625f : -1e10f;
        float s4 = -3e38f;
        if (j == 0) {
            float2 t4 = pb2[(g8 + 32) * 4 + g8];
            s4 = Fsm[lq0 + g8 + 32] ? (t4.x + t4.y) * 0.0625f : -1e10f;
        }

        float mx = fmaxf(fmaxf(fmaxf(s0, s1), fmaxf(s2, s3)), s4);
        mx = fmaxf(mx, __shfl_xor_sync(0xffffffffu, mx, 4));
        mx = fmaxf(mx, __shfl_xor_sync(0xffffffffu, mx, 2));
        mx = fmaxf(mx, __shfl_xor_sync(0xffffffffu, mx, 1));

        float e0 = __expf(s0 - mx);
        float e1 = __expf(s1 - mx);
        float e2 = __expf(s2 - mx);
        float e3 = __expf(s3 - mx);
        float e4 = (j == 0) ? __expf(s4 - mx) : 0.f;

        float sum = ((e0 + e1) + (e2 + e3)) + e4;
        sum += __shfl_xor_sync(0xffffffffu, sum, 4);
        sum += __shfl_xor_sync(0xffffffffu, sum, 2);
        sum += __shfl_xor_sync(0xffffffffu, sum, 1);
        float inv = 1.f / sum;

        float p0 = e0 * inv, p1 = e1 * inv, p2 = e2 * inv, p3 = e3 * inv;
        pf2[m0 * 4 + g8]        = pack2(p0);
        pf2[(m0 + 8) * 4 + g8]  = pack2(p1);
        pf2[(m0 + 16) * 4 + g8] = pack2(p2);
        pf2[(m0 + 24) * 4 + g8] = pack2(p3);

        float* po = out_p + (size_t)(b * S_LEN + gq) * W_SZ;
        po[j]      = p0;
        po[j + 8]  = p1;
        po[j + 16] = p2;
        po[j + 24] = p3;
        if (j == 0) {
            float p4 = e4 * inv;
            pf2[(g8 + 32) * 4 + g8] = pack2(p4);
            po[32] = p4;
        }
    }

    // V resident + visible block-wide before pass 2 (also publishes pf2)
    asm volatile("cp.async.wait_group 0;" ::: "memory");
    __syncthreads();

    // ---- pass 2: V + packed-p both prefetched; no pack ops in loop ----
    ulonglong2 acc[QW][2];
    #pragma unroll
    for (int q = 0; q < QW; ++q) {
        acc[q][0].x = 0ull; acc[q][0].y = 0ull;
        acc[q][1].x = 0ull; acc[q][1].y = 0ull;
    }

    const ulonglong2* Vsm2 = reinterpret_cast<const ulonglong2*>(Vsm);
    const ulonglong2* pf2u = reinterpret_cast<const ulonglong2*>(s2p);  // [NR][2]

    ulonglong2 v0 = Vsm2[(size_t)lq0 * D4 + 2 * lane];
    ulonglong2 v1 = Vsm2[(size_t)lq0 * D4 + 2 * lane + 1];
    ulonglong2 pa = pf2u[0];
    ulonglong2 pb = pf2u[1];

    #pragma unroll 4
    for (int r = 0; r < NR; ++r) {   // 36
        ulonglong2 v0n, v1n, pan, pbn;
        if (r + 1 < NR) {
            const ulonglong2* vn = Vsm2 + (size_t)(lq0 + r + 1) * D4 + 2 * lane;
            v0n = vn[0];
            v1n = vn[1];
            pan = pf2u[(r + 1) * 2];
            pbn = pf2u[(r + 1) * 2 + 1];
        }
        acc[0][0].x = fma2(pa.x, v0.x, acc[0][0].x);
        acc[0][0].y = fma2(pa.x, v0.y, acc[0][0].y);
        acc[0][1].x = fma2(pa.x, v1.x, acc[0][1].x);
        acc[0][1].y = fma2(pa.x, v1.y, acc[0][1].y);
        acc[1][0].x = fma2(pa.y, v0.x, acc[1][0].x);
        acc[1][0].y = fma2(pa.y, v0.y, acc[1][0].y);
        acc[1][1].x = fma2(pa.y, v1.x, acc[1][1].x);
        acc[1][1].y = fma2(pa.y, v1.y, acc[1][1].y);
        acc[2][0].x = fma2(pb.x, v0.x, acc[2][0].x);
        acc[2][0].y = fma2(pb.x, v0.y, acc[2][0].y);
        acc[2][1].x = fma2(pb.x, v1.x, acc[2][1].x);
        acc[2][1].y = fma2(pb.x, v1.y, acc[2][1].y);
        acc[3][0].x = fma2(pb.y, v0.x, acc[3][0].x);
        acc[3][0].y = fma2(pb.y, v0.y, acc[3][0].y);
        acc[3][1].x = fma2(pb.y, v1.x, acc[3][1].x);
        acc[3][1].y = fma2(pb.y, v1.y, acc[3][1].y);
        v0 = v0n;
        v1 = v1n;
        pa = pan;
        pb = pbn;
    }

    ulonglong2* obase = reinterpret_cast<ulonglong2*>(
        out_vals + ((size_t)b * S_LEN + base + lq0) * D_DIM);
    #pragma unroll
    for (int q = 0; q < QW; ++q) {
        obase[q * D4 + 2 * lane]     = acc[q][0];
        obase[q * D4 + 2 * lane + 1] = acc[q][1];
    }
}

extern "C" void kernel_launch(void* const* d_in, const int* in_sizes, int n_in,
                              void* d_out, int out_size)
{
    const float* q    = (const float*)d_in[0];
    const float* k    = (const float*)d_in[1];
    const float* v    = (const float*)d_in[2];
    const int*   mask = (const int*)d_in[3];

    float* out_vals = (float*)d_out;
    float* out_p    = out_vals + (size_t)B_SZ * S_LEN * D_DIM;

    static bool attr_set = false;
    if (!attr_set) {
        cudaFuncSetAttribute(local_attn_kernel,
                             cudaFuncAttributeMaxDynamicSharedMemorySize,
                             SMEM_BYTES);
        attr_set = true;
    }

    dim3 grid(S_LEN / TILE_Q, B_SZ);   // (32, 4) = 128 CTAs, one wave
    local_attn_kernel<<<grid, THREADS, SMEM_BYTES>>>(q, k, v, mask, out_vals, out_p);
}